// round 2
// baseline (speedup 1.0000x reference)
#include <cuda_runtime.h>
#include <cstdint>

#define TABLE_SIZE 524288u          // 2^19 -> modulo is a mask
#define NUM_LEVELS 16
#define N_POINTS (1u << 20)
#define HASH_PRIME 2654435761u

#define N_STAGED_LEVELS 6           // levels 0..5 (res 16..64) staged in smem
#define STAGE_ENTRIES 9552u         // sum (res_l+1)^2, l=0..5
#define STAGE_BYTES (STAGE_ENTRIES * 8u)

#define BLOCK 512
#define GRID  304                   // 2 CTAs/SM x 152 SMs (grid-stride safe anyway)

// scalings[l] = floor(16 * (2^0.4)^l) computed in fp32 as the reference does.
__constant__ float kScale[NUM_LEVELS] = {
    16.0f, 21.0f, 27.0f, 36.0f, 48.0f, 64.0f, 84.0f, 111.0f,
    147.0f, 194.0f, 256.0f, 337.0f, 445.0f, 588.0f, 776.0f, 1024.0f
};

// Staged-level grid widths (res+1) and prefix offsets into smem.
__constant__ uint32_t kW[N_STAGED_LEVELS]   = {17u, 22u, 28u, 37u, 49u, 65u};
__constant__ uint32_t kOff[N_STAGED_LEVELS] = {0u, 289u, 773u, 1557u, 2926u, 5327u};

__global__ __launch_bounds__(BLOCK)
void hash_encode_kernel(const float2* __restrict__ x,
                        const float2* __restrict__ table,
                        float2* __restrict__ out)
{
    extern __shared__ float2 s_tab[];   // 9552 entries, levels 0..5 direct-indexed

    const uint32_t tid = threadIdx.x;

    // ---- Stage low-level tables into shared memory (direct vertex indexing) ----
    for (uint32_t i = tid; i < STAGE_ENTRIES; i += BLOCK) {
        uint32_t l = (i >= 289u) + (i >= 773u) + (i >= 1557u) +
                     (i >= 2926u) + (i >= 5327u);
        const uint32_t within = i - kOff[l];
        const uint32_t W  = kW[l];
        const uint32_t vx = within / W;
        const uint32_t vy = within - vx * W;
        const uint32_t h  = ((vx ^ (vy * HASH_PRIME)) & (TABLE_SIZE - 1u))
                            + l * TABLE_SIZE;
        s_tab[i] = __ldg(&table[h]);
    }
    __syncthreads();

    // ---- Main loop: thread = (point-slot, level); level fixed per thread ----
    const uint32_t l  = tid & 15u;
    const uint32_t pr = tid >> 4;                 // 0..31 point slot in block-group
    const float    s  = kScale[l];
    const bool     lo = (l < N_STAGED_LEVELS);
    const uint32_t W    = lo ? kW[l]  : 0u;
    const uint32_t soff = lo ? kOff[l] : 0u;
    const uint32_t base = l * TABLE_SIZE;

    const uint32_t PB = N_POINTS >> 5;            // 32768 point-blocks of 32

    for (uint32_t pb = blockIdx.x; pb < PB; pb += gridDim.x) {
        const uint32_t p  = (pb << 5) + pr;
        const float2   xp = __ldg(&x[p]);         // 16 lanes broadcast same point

        const float sx = xp.x * s;
        const float sy = xp.y * s;

        const float fxf = floorf(sx);
        const float fyf = floorf(sy);
        const float cxf = ceilf(sx);
        const float cyf = ceilf(sy);

        const uint32_t fx = (uint32_t)(int32_t)fxf;
        const uint32_t fy = (uint32_t)(int32_t)fyf;
        const uint32_t cx = (uint32_t)(int32_t)cxf;
        const uint32_t cy = (uint32_t)(int32_t)cyf;

        const float ox = sx - fxf;
        const float oy = sy - fyf;

        float2 f0, f1, f2, f3;                    // v0=(cx,cy) v1=(cx,fy) v2=(fx,cy) v3=(fx,fy)
        if (lo) {
            const uint32_t rc = soff + cx * W;
            const uint32_t rf = soff + fx * W;
            f0 = s_tab[rc + cy];
            f1 = s_tab[rc + fy];
            f2 = s_tab[rf + cy];
            f3 = s_tab[rf + fy];
        } else {
            const uint32_t hyc = cy * HASH_PRIME;
            const uint32_t hyf = fy * HASH_PRIME;
            const uint32_t h0 = ((cx ^ hyc) & (TABLE_SIZE - 1u)) + base;
            const uint32_t h1 = ((cx ^ hyf) & (TABLE_SIZE - 1u)) + base;
            const uint32_t h2 = ((fx ^ hyc) & (TABLE_SIZE - 1u)) + base;
            const uint32_t h3 = ((fx ^ hyf) & (TABLE_SIZE - 1u)) + base;
            f0 = __ldg(&table[h0]);
            f1 = __ldg(&table[h1]);
            f2 = __ldg(&table[h2]);
            f3 = __ldg(&table[h3]);
        }

        const float omx = 1.0f - ox;
        const float omy = 1.0f - oy;

        float2 e;
        {
            const float f03x = f0.x * ox + f3.x * omx;
            const float f12x = f1.x * ox + f2.x * omx;
            e.x = f03x * oy + f12x * omy;
            const float f03y = f0.y * ox + f3.y * omx;
            const float f12y = f1.y * ox + f2.y * omx;
            e.y = f03y * oy + f12y * omy;
        }

        // out float2 index = p*16 + l = pb*512 + tid -> fully coalesced
        out[(p << 4) + l] = e;
    }
}

extern "C" void kernel_launch(void* const* d_in, const int* in_sizes, int n_in,
                              void* d_out, int out_size)
{
    const float2* x     = (const float2*)d_in[0];   // (N_POINTS, 2) float32
    const float2* table = (const float2*)d_in[1];   // (TABLE_SIZE*NUM_LEVELS, 2) float32
    float2* out = (float2*)d_out;                   // (N_POINTS, 32) float32

    // >48KB dynamic smem requires opting in (idempotent, capture-safe).
    cudaFuncSetAttribute(hash_encode_kernel,
                         cudaFuncAttributeMaxDynamicSharedMemorySize, STAGE_BYTES);

    hash_encode_kernel<<<GRID, BLOCK, STAGE_BYTES>>>(x, table, out);
}

// round 3
// speedup vs baseline: 1.4407x; 1.4407x over previous
#include <cuda_runtime.h>
#include <cstdint>

#define TABLE_SIZE 524288u          // 2^19 -> modulo is a mask
#define NUM_LEVELS 16
#define N_POINTS (1u << 20)
#define HASH_PRIME 2654435761u

// ---- low-level (staged) kernel config: levels 0..5, res 16..64 ----
#define N_LOW 6
#define STAGE_ENTRIES 9552u         // sum (res_l+1)^2, l=0..5
#define STAGE_BYTES   (STAGE_ENTRIES * 8u)
#define L_BLOCK 1024
#define L_GRID  304                 // 2 CTAs/SM x 152 SMs, persistent grid-stride
#define L_TOTAL (N_POINTS * N_LOW)  // 6,291,456 threads of work

// ---- high-level kernel config: levels 6..15 ----
#define N_HIGH 10
#define H_TOTAL (N_POINTS * N_HIGH) // 10,485,760
#define H_BLOCK 256

// scalings: floor(16 * (2^0.4)^l) in fp32, matching the reference exactly.
__constant__ float kScaleLow[N_LOW] = {
    16.0f, 21.0f, 27.0f, 36.0f, 48.0f, 64.0f
};
__constant__ float kScaleHigh[N_HIGH] = {
    84.0f, 111.0f, 147.0f, 194.0f, 256.0f,
    337.0f, 445.0f, 588.0f, 776.0f, 1024.0f
};

// staged-level grid widths (res+1) and prefix offsets into smem
__constant__ uint32_t kW[N_LOW]   = {17u, 22u, 28u, 37u, 49u, 65u};
__constant__ uint32_t kOff[N_LOW] = {0u, 289u, 773u, 1557u, 2926u, 5327u};

// ===================== HIGH LEVELS: pure divergent LDG =====================
__global__ __launch_bounds__(H_BLOCK)
void hash_encode_high(const float2* __restrict__ x,
                      const float2* __restrict__ table,
                      float2* __restrict__ out)
{
    const uint32_t t = blockIdx.x * H_BLOCK + threadIdx.x;
    if (t >= H_TOTAL) return;

    const uint32_t p  = t / N_HIGH;            // const-div -> mulhi
    const uint32_t li = t - p * N_HIGH;        // 0..9
    const uint32_t l  = li + 6u;

    const float2 xp = __ldg(&x[p]);            // ~3 points/warp -> broadcast
    const float  s  = kScaleHigh[li];

    const float sx = xp.x * s;
    const float sy = xp.y * s;

    const float fxf = floorf(sx);
    const float fyf = floorf(sy);
    const float cxf = ceilf(sx);
    const float cyf = ceilf(sy);

    const uint32_t fx = (uint32_t)(int32_t)fxf;
    const uint32_t fy = (uint32_t)(int32_t)fyf;
    const uint32_t cx = (uint32_t)(int32_t)cxf;
    const uint32_t cy = (uint32_t)(int32_t)cyf;

    const float ox = sx - fxf;
    const float oy = sy - fyf;

    const uint32_t base = l * TABLE_SIZE;
    const uint32_t hyc  = cy * HASH_PRIME;
    const uint32_t hyf  = fy * HASH_PRIME;

    // v0=(cx,cy) v1=(cx,fy) v2=(fx,cy) v3=(fx,fy)
    const uint32_t h0 = ((cx ^ hyc) & (TABLE_SIZE - 1u)) + base;
    const uint32_t h1 = ((cx ^ hyf) & (TABLE_SIZE - 1u)) + base;
    const uint32_t h2 = ((fx ^ hyc) & (TABLE_SIZE - 1u)) + base;
    const uint32_t h3 = ((fx ^ hyf) & (TABLE_SIZE - 1u)) + base;

    const float2 f0 = __ldg(&table[h0]);
    const float2 f1 = __ldg(&table[h1]);
    const float2 f2 = __ldg(&table[h2]);
    const float2 f3 = __ldg(&table[h3]);

    const float omx = 1.0f - ox;
    const float omy = 1.0f - oy;

    float2 e;
    e.x = (f0.x * ox + f3.x * omx) * oy + (f1.x * ox + f2.x * omx) * omy;
    e.y = (f0.y * ox + f3.y * omx) * oy + (f1.y * ox + f2.y * omx) * omy;

    out[(p << 4) + l] = e;                     // row p's line, bytes 48..127
}

// ===================== LOW LEVELS: smem direct-indexed =====================
__global__ __launch_bounds__(L_BLOCK)
void hash_encode_low(const float2* __restrict__ x,
                     const float2* __restrict__ table,
                     float2* __restrict__ out)
{
    extern __shared__ float2 s_tab[];          // 9552 entries, levels 0..5

    const uint32_t tid = threadIdx.x;

    // stage: hash each low-level vertex once, store direct-indexed
    for (uint32_t i = tid; i < STAGE_ENTRIES; i += L_BLOCK) {
        uint32_t l = (i >= 289u) + (i >= 773u) + (i >= 1557u) +
                     (i >= 2926u) + (i >= 5327u);
        const uint32_t within = i - kOff[l];
        const uint32_t W  = kW[l];
        const uint32_t vx = within / W;
        const uint32_t vy = within - vx * W;
        const uint32_t h  = ((vx ^ (vy * HASH_PRIME)) & (TABLE_SIZE - 1u))
                            + l * TABLE_SIZE;
        s_tab[i] = __ldg(&table[h]);
    }
    __syncthreads();

    for (uint32_t t = blockIdx.x * L_BLOCK + tid; t < L_TOTAL;
         t += L_GRID * L_BLOCK) {
        const uint32_t p = t / N_LOW;          // const-div -> mulhi
        const uint32_t l = t - p * N_LOW;      // 0..5

        const float2 xp = __ldg(&x[p]);        // ~5 points/warp -> broadcast
        const float  s  = kScaleLow[l];

        const float sx = xp.x * s;
        const float sy = xp.y * s;

        const float fxf = floorf(sx);
        const float fyf = floorf(sy);
        const float cxf = ceilf(sx);
        const float cyf = ceilf(sy);

        const uint32_t fx = (uint32_t)(int32_t)fxf;
        const uint32_t fy = (uint32_t)(int32_t)fyf;
        const uint32_t cx = (uint32_t)(int32_t)cxf;
        const uint32_t cy = (uint32_t)(int32_t)cyf;

        const float ox = sx - fxf;
        const float oy = sy - fyf;

        const uint32_t W    = kW[l];
        const uint32_t soff = kOff[l];
        const uint32_t rc   = soff + cx * W;
        const uint32_t rf   = soff + fx * W;

        const float2 f0 = s_tab[rc + cy];
        const float2 f1 = s_tab[rc + fy];
        const float2 f2 = s_tab[rf + cy];
        const float2 f3 = s_tab[rf + fy];

        const float omx = 1.0f - ox;
        const float omy = 1.0f - oy;

        float2 e;
        e.x = (f0.x * ox + f3.x * omx) * oy + (f1.x * ox + f2.x * omx) * omy;
        e.y = (f0.y * ox + f3.y * omx) * oy + (f1.y * ox + f2.y * omx) * omy;

        out[(p << 4) + l] = e;                 // row p's line, bytes 0..47
    }
}

extern "C" void kernel_launch(void* const* d_in, const int* in_sizes, int n_in,
                              void* d_out, int out_size)
{
    const float2* x     = (const float2*)d_in[0];   // (N_POINTS, 2) float32
    const float2* table = (const float2*)d_in[1];   // (TABLE_SIZE*16, 2) float32
    float2* out = (float2*)d_out;                   // (N_POINTS, 32) float32

    cudaFuncSetAttribute(hash_encode_low,
                         cudaFuncAttributeMaxDynamicSharedMemorySize, STAGE_BYTES);

    const uint32_t h_grid = (H_TOTAL + H_BLOCK - 1) / H_BLOCK;  // 40960
    hash_encode_high<<<h_grid, H_BLOCK>>>(x, table, out);
    hash_encode_low <<<L_GRID, L_BLOCK, STAGE_BYTES>>>(x, table, out);
}

// round 4
// speedup vs baseline: 1.6004x; 1.1108x over previous
#include <cuda_runtime.h>
#include <cstdint>

#define TABLE_SIZE 524288u          // 2^19 -> modulo is a mask
#define NUM_LEVELS 16
#define N_POINTS (1u << 20)
#define HASH_PRIME 2654435761u

// Stage levels 0..4 (res 16,21,27,36,48): sum (res+1)^2 = 5327 entries = 42.6KB
#define N_STAGED 5
#define STAGE_ENTRIES 5327u
#define STAGE_BYTES   (STAGE_ENTRIES * 8u)

#define BLOCK 512
#define CTAS_PER_SM 4
#define GRID (152 * CTAS_PER_SM)    // 608 persistent CTAs
#define POINT_BLOCKS (N_POINTS / 32u)   // 32768, each = 32 points x 16 levels

// scalings: floor(16 * (2^0.4)^l) in fp32, matching the reference exactly.
__constant__ float kScale[NUM_LEVELS] = {
    16.0f, 21.0f, 27.0f, 36.0f, 48.0f, 64.0f, 84.0f, 111.0f,
    147.0f, 194.0f, 256.0f, 337.0f, 445.0f, 588.0f, 776.0f, 1024.0f
};
// staged-level grid widths (res+1) and prefix offsets into smem
__constant__ uint32_t kW[N_STAGED]   = {17u, 22u, 28u, 37u, 49u};
__constant__ uint32_t kOff[N_STAGED] = {0u, 289u, 773u, 1557u, 2926u};

__global__ __launch_bounds__(BLOCK, CTAS_PER_SM)
void hash_encode_kernel(const float2* __restrict__ x,
                        const float2* __restrict__ table,
                        float2* __restrict__ out)
{
    extern __shared__ float2 s_tab[];          // 5327 entries, levels 0..4

    const uint32_t tid = threadIdx.x;

    // ---- Stage levels 0..4, direct vertex indexing (hash computed once) ----
    for (uint32_t i = tid; i < STAGE_ENTRIES; i += BLOCK) {
        const uint32_t l = (i >= 289u) + (i >= 773u) + (i >= 1557u) + (i >= 2926u);
        const uint32_t within = i - kOff[l];
        const uint32_t W  = kW[l];
        const uint32_t vx = within / W;
        const uint32_t vy = within - vx * W;
        const uint32_t h  = ((vx ^ (vy * HASH_PRIME)) & (TABLE_SIZE - 1u))
                            + l * TABLE_SIZE;
        s_tab[i] = __ldg(&table[h]);
    }
    __syncthreads();

    // ---- Fused main loop: lane = (point-slot, level), level fixed ----
    const uint32_t l  = tid & 15u;
    const uint32_t pr = tid >> 4;              // 0..31 point slot
    const float    s  = kScale[l];
    const bool     lo = (l < N_STAGED);
    const uint32_t Wl   = lo ? kW[l]   : 0u;
    const uint32_t soff = lo ? kOff[l] : 0u;
    const uint32_t base = l * TABLE_SIZE;

    for (uint32_t pb = blockIdx.x; pb < POINT_BLOCKS; pb += GRID) {
        const uint32_t p  = (pb << 5) + pr;
        const float2   xp = __ldg(&x[p]);      // 16 lanes broadcast same point

        const float sx = xp.x * s;
        const float sy = xp.y * s;

        const float fxf = floorf(sx);
        const float fyf = floorf(sy);
        const float cxf = ceilf(sx);
        const float cyf = ceilf(sy);

        const uint32_t fx = (uint32_t)(int32_t)fxf;
        const uint32_t fy = (uint32_t)(int32_t)fyf;
        const uint32_t cx = (uint32_t)(int32_t)cxf;
        const uint32_t cy = (uint32_t)(int32_t)cyf;

        const float ox = sx - fxf;
        const float oy = sy - fyf;

        float2 f0, f1, f2, f3;   // v0=(cx,cy) v1=(cx,fy) v2=(fx,cy) v3=(fx,fy)
        if (lo) {
            const uint32_t rc = soff + cx * Wl;
            const uint32_t rf = soff + fx * Wl;
            f0 = s_tab[rc + cy];
            f1 = s_tab[rc + fy];
            f2 = s_tab[rf + cy];
            f3 = s_tab[rf + fy];
        } else {
            const uint32_t hyc = cy * HASH_PRIME;
            const uint32_t hyf = fy * HASH_PRIME;
            const uint32_t h0 = ((cx ^ hyc) & (TABLE_SIZE - 1u)) + base;
            const uint32_t h1 = ((cx ^ hyf) & (TABLE_SIZE - 1u)) + base;
            const uint32_t h2 = ((fx ^ hyc) & (TABLE_SIZE - 1u)) + base;
            const uint32_t h3 = ((fx ^ hyf) & (TABLE_SIZE - 1u)) + base;
            f0 = __ldg(&table[h0]);
            f1 = __ldg(&table[h1]);
            f2 = __ldg(&table[h2]);
            f3 = __ldg(&table[h3]);
        }

        const float omx = 1.0f - ox;
        const float omy = 1.0f - oy;

        float2 e;
        e.x = (f0.x * ox + f3.x * omx) * oy + (f1.x * ox + f2.x * omx) * omy;
        e.y = (f0.y * ox + f3.y * omx) * oy + (f1.y * ox + f2.y * omx) * omy;

        // out float2 index = p*16 + l = pb*512 + tid -> fully coalesced 256B/warp
        out[(p << 4) + l] = e;
    }
}

extern "C" void kernel_launch(void* const* d_in, const int* in_sizes, int n_in,
                              void* d_out, int out_size)
{
    const float2* x     = (const float2*)d_in[0];   // (N_POINTS, 2) float32
    const float2* table = (const float2*)d_in[1];   // (TABLE_SIZE*16, 2) float32
    float2* out = (float2*)d_out;                   // (N_POINTS, 32) float32

    cudaFuncSetAttribute(hash_encode_kernel,
                         cudaFuncAttributeMaxDynamicSharedMemorySize, STAGE_BYTES);

    hash_encode_kernel<<<GRID, BLOCK, STAGE_BYTES>>>(x, table, out);
}